// round 2
// baseline (speedup 1.0000x reference)
#include <cuda_runtime.h>
#include <cstdint>

// Deterministic cross-chunk reduction scratch (no alloc, no float atomics).
#define MAX_B      64
#define MAX_CHUNKS 32
__device__ float g_partial_log[MAX_B * MAX_CHUNKS];
__device__ float g_partial_hit[MAX_B * MAX_CHUNKS];
__device__ int   g_count[MAX_B];          // zero-init; self-resetting per replay

#define THREADS 256

__global__ __launch_bounds__(THREADS)
void traj_score_fused(const float* __restrict__ u_pred,
                      const float* __restrict__ u_obs,
                      const float* __restrict__ h_arr,
                      const float* __restrict__ lam_arr,
                      const float* __restrict__ th_arr,
                      float* __restrict__ out,
                      int n_per, int chunk, int n_chunks, int B)
{
    const int e = blockIdx.x;           // element / segment id
    const int c = blockIdx.y;           // chunk id within segment
    const int start = c * chunk;
    int end = start + chunk;
    if (end > n_per) end = n_per;
    const int count = end - start;

    // Per-element constants
    const float h    = __ldg(&h_arr[e]);
    const float lam  = __ldg(&lam_arr[e]);
    const float th   = __ldg(&th_arr[e]);
    const float inv_th = 1.0f / th;
    const float coef = lam / (1.0f - __expf(-lam));   // lam / (1 - e^-lam)
    const float A    = h * coef;                      // p_hit = A * exp(-lam*v)
    const float c1   = 1.0f - h;

    const size_t base_obs = (size_t)e * (size_t)n_per + (size_t)start;

    float acc_log = 0.0f;
    float acc_hit = 0.0f;

    const int tid = threadIdx.x;

    // Fast path: 4 observations per iteration via 3x float4 per array.
    int scalar_begin = 0;
    if ((base_obs & 3u) == 0u) {
        const int n_groups = count >> 2;           // groups of 4 obs
        scalar_begin = n_groups << 2;
        const float4* __restrict__ p4 = (const float4*)(u_pred + base_obs * 3);
        const float4* __restrict__ o4 = (const float4*)(u_obs  + base_obs * 3);

        #pragma unroll 2
        for (int g = tid; g < n_groups; g += THREADS) {
            const size_t fb = (size_t)g * 3;
            float4 a0 = __ldg(&p4[fb + 0]);
            float4 a1 = __ldg(&p4[fb + 1]);
            float4 a2 = __ldg(&p4[fb + 2]);
            float4 b0 = __ldg(&o4[fb + 0]);
            float4 b1 = __ldg(&o4[fb + 1]);
            float4 b2 = __ldg(&o4[fb + 2]);

            float dx[4], dy[4], dz[4];
            dx[0] = a0.x - b0.x; dy[0] = a0.y - b0.y; dz[0] = a0.z - b0.z;
            dx[1] = a0.w - b0.w; dy[1] = a1.x - b1.x; dz[1] = a1.y - b1.y;
            dx[2] = a1.z - b1.z; dy[2] = a1.w - b1.w; dz[2] = a2.x - b2.x;
            dx[3] = a2.y - b2.y; dy[3] = a2.z - b2.z; dz[3] = a2.w - b2.w;

            #pragma unroll
            for (int j = 0; j < 4; ++j) {
                float s2 = dx[j]*dx[j];
                s2 = fmaf(dy[j], dy[j], s2);
                s2 = fmaf(dz[j], dz[j], s2);
                const bool close = s2 < th;
                const float v   = s2 * inv_th;
                const float em  = __expf(-lam * v);
                const float ph  = A * em;
                const float p   = ph + c1;
                const float lp  = __logf(p);
                const float post = __fdividef(ph, p);
                acc_log += close ? lp : 0.0f;
                acc_hit += (close && post > 0.95f) ? post : 0.0f;
            }
        }
    }

    // Scalar tail (covers misaligned bases and count % 4)
    for (int i = scalar_begin + tid; i < count; i += THREADS) {
        const size_t o = (base_obs + (size_t)i) * 3;
        const float dx = __ldg(&u_pred[o + 0]) - __ldg(&u_obs[o + 0]);
        const float dy = __ldg(&u_pred[o + 1]) - __ldg(&u_obs[o + 1]);
        const float dz = __ldg(&u_pred[o + 2]) - __ldg(&u_obs[o + 2]);
        float s2 = dx*dx; s2 = fmaf(dy, dy, s2); s2 = fmaf(dz, dz, s2);
        const bool close = s2 < th;
        const float v   = s2 * inv_th;
        const float em  = __expf(-lam * v);
        const float ph  = A * em;
        const float p   = ph + c1;
        const float lp  = __logf(p);
        const float post = __fdividef(ph, p);
        acc_log += close ? lp : 0.0f;
        acc_hit += (close && post > 0.95f) ? post : 0.0f;
    }

    // Deterministic block reduction (fixed shuffle tree)
    __shared__ float s_log[THREADS / 32];
    __shared__ float s_hit[THREADS / 32];
    __shared__ int   s_last;
    const int lane = tid & 31;
    const int wid  = tid >> 5;
    #pragma unroll
    for (int off = 16; off > 0; off >>= 1) {
        acc_log += __shfl_down_sync(0xFFFFFFFFu, acc_log, off);
        acc_hit += __shfl_down_sync(0xFFFFFFFFu, acc_hit, off);
    }
    if (lane == 0) { s_log[wid] = acc_log; s_hit[wid] = acc_hit; }
    __syncthreads();
    if (wid == 0) {
        float vlog = (lane < THREADS / 32) ? s_log[lane] : 0.0f;
        float vhit = (lane < THREADS / 32) ? s_hit[lane] : 0.0f;
        #pragma unroll
        for (int off = 16; off > 0; off >>= 1) {
            vlog += __shfl_down_sync(0xFFFFFFFFu, vlog, off);
            vhit += __shfl_down_sync(0xFFFFFFFFu, vhit, off);
        }
        if (lane == 0) {
            g_partial_log[e * MAX_CHUNKS + c] = vlog;
            g_partial_hit[e * MAX_CHUNKS + c] = vhit;
            __threadfence();
            // last-block-done: old == n_chunks-1 means all partials visible
            int old = atomicAdd(&g_count[e], 1);
            s_last = (old == n_chunks - 1) ? 1 : 0;
        }
    }
    __syncthreads();

    if (s_last) {
        // Finisher block: deterministic fixed-tree sum over chunk partials.
        if (wid == 0) {
            __threadfence();  // acquire partials
            float vlog = (lane < n_chunks) ? g_partial_log[e * MAX_CHUNKS + lane] : 0.0f;
            float vhit = (lane < n_chunks) ? g_partial_hit[e * MAX_CHUNKS + lane] : 0.0f;
            #pragma unroll
            for (int off = 16; off > 0; off >>= 1) {
                vlog += __shfl_down_sync(0xFFFFFFFFu, vlog, off);
                vhit += __shfl_down_sync(0xFFFFFFFFu, vhit, off);
            }
            if (lane == 0) {
                out[e]         = vlog;   // log_like
                out[B + e]     = vhit;   // hits
                out[2 * B + e] = vhit;   // hits_raw
                g_count[e] = 0;          // reset for next graph replay
            }
        }
    }
}

extern "C" void kernel_launch(void* const* d_in, const int* in_sizes, int n_in,
                              void* d_out, int out_size)
{
    const float* u_pred = (const float*)d_in[0];
    const float* u_obs  = (const float*)d_in[1];
    const float* h      = (const float*)d_in[2];
    const float* lam    = (const float*)d_in[3];
    const float* th     = (const float*)d_in[4];

    const int N = in_sizes[0] / 3;          // observations
    const int B = in_sizes[2];              // elements (64)
    const int n_per = N / B;                // 100000

    int n_chunks = 25;                      // must be <= 32 (warp-tree finisher)
    if (n_chunks > MAX_CHUNKS) n_chunks = MAX_CHUNKS;
    int chunk = (n_per + n_chunks - 1) / n_chunks;
    chunk = (chunk + 3) & ~3;               // multiple of 4 keeps float4 alignment
    n_chunks = (n_per + chunk - 1) / chunk;

    dim3 grid(B, n_chunks);
    traj_score_fused<<<grid, THREADS>>>(u_pred, u_obs, h, lam, th,
                                        (float*)d_out, n_per, chunk, n_chunks, B);
}